// round 1
// baseline (speedup 1.0000x reference)
#include <cuda_runtime.h>
#include <math.h>

#define BATCH 64
#define N 256
#define NT 256
#define INF_F 1e30f

// per-batch matched-distance sums (deterministic, no atomics)
__device__ float g_batch_sum[BATCH];

__global__ void __launch_bounds__(NT, 1)
hungarian_kernel(const float* __restrict__ pred,
                 const float* __restrict__ target)
{
    const int b = blockIdx.x;
    const int t = threadIdx.x;      // thread t owns column j = t+1 (1-based)
    const int j = t + 1;

    __shared__ float spx[N], spy[N], spz[N];   // pred points (rows)
    __shared__ float su[N + 1];                // row potentials u[0..N]
    __shared__ int   sp[N + 1];                // p[j] = row matched to column j
    __shared__ int   sway[N + 1];              // way[j]
    __shared__ float rbuf_val[8];
    __shared__ int   rbuf_idx[8];
    __shared__ float s_delta;
    __shared__ int   s_j1;

    // ---- load points ----
    const float* pb = pred   + (size_t)b * N * 3;
    const float* tb = target + (size_t)b * N * 3;
    spx[t] = pb[t * 3 + 0];
    spy[t] = pb[t * 3 + 1];
    spz[t] = pb[t * 3 + 2];
    const float tx = tb[t * 3 + 0];
    const float ty = tb[t * 3 + 1];
    const float tz = tb[t * 3 + 2];

    su[t] = 0.0f;
    sp[t] = 0;
    if (t == 0) { su[N] = 0.0f; sp[N] = 0; }
    float v = 0.0f;                 // column potential v[j] (register)
    __syncthreads();

    // ---- JV Hungarian: rows 1..N ----
    for (int i = 1; i <= N; ++i) {
        if (t == 0) sp[0] = i;
        float minv = INF_F;         // minv[j] (register)
        bool  used = false;         // used[j] (register); column 0 handled by t==0
        __syncthreads();

        int j0 = 0;
        for (;;) {
            // mark used[j0]
            if (j == j0) used = true;
            const int i0 = sp[j0];  // sp stable inside inner loop

            // cur = a[i0-1][j-1] - u[i0] - v[j], update minv/way
            if (!used) {
                const float dx = spx[i0 - 1] - tx;
                const float dy = spy[i0 - 1] - ty;
                const float dz = spz[i0 - 1] - tz;
                const float cur = sqrtf(dx * dx + dy * dy + dz * dz) - su[i0] - v;
                if (cur < minv) { minv = cur; sway[j] = j0; }
            }

            // ---- block argmin over free columns ----
            float val = used ? INF_F : minv;
            int   idx = j;
            #pragma unroll
            for (int o = 16; o > 0; o >>= 1) {
                const float oval = __shfl_down_sync(0xffffffffu, val, o);
                const int   oidx = __shfl_down_sync(0xffffffffu, idx, o);
                if (oval < val) { val = oval; idx = oidx; }
            }
            if ((t & 31) == 0) { rbuf_val[t >> 5] = val; rbuf_idx[t >> 5] = idx; }
            __syncthreads();
            if (t == 0) {
                float bv = rbuf_val[0]; int bi = rbuf_idx[0];
                #pragma unroll
                for (int w = 1; w < 8; ++w)
                    if (rbuf_val[w] < bv) { bv = rbuf_val[w]; bi = rbuf_idx[w]; }
                s_delta = bv; s_j1 = bi;
            }
            __syncthreads();
            const float delta = s_delta;
            const int   j1    = s_j1;

            // ---- potential updates ----
            if (used) {
                su[sp[j]] += delta;   // distinct rows per used column: no conflict
                v -= delta;
            } else {
                minv -= delta;
            }
            if (t == 0) su[sp[0]] += delta;   // column 0 is always used

            j0 = j1;
            __syncthreads();          // su writes visible before next cur read
            if (sp[j0] == 0) break;   // reached a free column
        }

        // ---- augment along way[] (serial, short path) ----
        if (t == 0) {
            int jj = j0;
            while (jj) {
                const int j1a = sway[jj];
                sp[jj] = sp[j1a];
                jj = j1a;
            }
        }
        __syncthreads();
    }

    // ---- matched distance for my column: row sp[j]-1 <-> target[j-1] ----
    const int r = sp[j] - 1;
    const float dx = spx[r] - tx;
    const float dy = spy[r] - ty;
    const float dz = spz[r] - tz;
    float md = sqrtf(dx * dx + dy * dy + dz * dz);

    #pragma unroll
    for (int o = 16; o > 0; o >>= 1)
        md += __shfl_down_sync(0xffffffffu, md, o);
    if ((t & 31) == 0) rbuf_val[t >> 5] = md;
    __syncthreads();
    if (t == 0) {
        float s = 0.0f;
        #pragma unroll
        for (int w = 0; w < 8; ++w) s += rbuf_val[w];
        g_batch_sum[b] = s;
    }
}

__global__ void finalize_kernel(float* __restrict__ out)
{
    double s = 0.0;
    #pragma unroll
    for (int b = 0; b < BATCH; ++b) s += (double)g_batch_sum[b];
    out[0] = (float)(s / (double)BATCH);
}

extern "C" void kernel_launch(void* const* d_in, const int* in_sizes, int n_in,
                              void* d_out, int out_size)
{
    const float* pred   = (const float*)d_in[0];
    const float* target = (const float*)d_in[1];
    float* out = (float*)d_out;

    hungarian_kernel<<<BATCH, NT>>>(pred, target);
    finalize_kernel<<<1, 1>>>(out);
}

// round 2
// speedup vs baseline: 2.5969x; 2.5969x over previous
#include <cuda_runtime.h>
#include <math.h>

#define BATCH 64
#define N 256
#define NT 256
#define INF_F 1e30f

// per-batch matched-distance sums (deterministic, no atomics)
__device__ float g_batch_sum[BATCH];

// order-preserving float <-> uint map (min on uint == min on float, non-NaN)
__device__ __forceinline__ unsigned fmap(float f) {
    unsigned b = __float_as_uint(f);
    return (b & 0x80000000u) ? ~b : (b | 0x80000000u);
}
__device__ __forceinline__ float funmap(unsigned m) {
    return __uint_as_float((m & 0x80000000u) ? (m & 0x7fffffffu) : ~m);
}

__global__ void __launch_bounds__(NT, 1)
hungarian_kernel(const float* __restrict__ pred,
                 const float* __restrict__ target)
{
    const int b = blockIdx.x;
    const int t = threadIdx.x;      // thread t owns column j = t+1 (1-based)
    const int j = t + 1;

    __shared__ float spx[N], spy[N], spz[N];     // pred points (rows)
    __shared__ float su[N + 1];                  // row potentials u[1..N]
    __shared__ short sp[N + 1];                  // p[j] = row matched to col j (1-based; 0=free)
    __shared__ short sway[N + 1];                // predecessor column on path
    __shared__ short sargr[N];                   // argmin row per column (0-based)
    __shared__ unsigned char srowm[N];           // row matched flag (prematch)
    __shared__ short sunm[N];                    // unmatched-row list (1-based)
    __shared__ int   s_nunm;
    __shared__ unsigned long long rbuf[2][8];    // double-buffered warp results
    __shared__ float fsum[8];

    // ---- load points ----
    const float* pb = pred   + (size_t)b * N * 3;
    const float* tb = target + (size_t)b * N * 3;
    spx[t] = pb[t * 3 + 0];
    spy[t] = pb[t * 3 + 1];
    spz[t] = pb[t * 3 + 2];
    const float tx = tb[t * 3 + 0];
    const float ty = tb[t * 3 + 1];
    const float tz = tb[t * 3 + 2];

    su[t] = 0.0f;
    sp[t] = 0;
    srowm[t] = 0;
    if (t == 0) { su[N] = 0.0f; sp[N] = 0; }
    __syncthreads();

    // ---- JV column reduction: v[j] = min_i c(i,j), remember argmin row ----
    float v = INF_F;
    int rmin = 0;
    #pragma unroll 4
    for (int i = 0; i < N; ++i) {
        const float dx = spx[i] - tx;
        const float dy = spy[i] - ty;
        const float dz = spz[i] - tz;
        const float d = sqrtf(fmaf(dx, dx, fmaf(dy, dy, dz * dz)));
        if (d < v) { v = d; rmin = i; }
    }
    sargr[t] = (short)rmin;
    __syncthreads();

    // ---- greedy pre-match on tight edges (serial, deterministic) ----
    if (t == 0) {
        for (int jj = 1; jj <= N; ++jj) {
            const int r = sargr[jj - 1];
            if (!srowm[r]) { srowm[r] = 1; sp[jj] = (short)(r + 1); }
        }
        int cnt = 0;
        for (int i = 0; i < N; ++i)
            if (!srowm[i]) sunm[cnt++] = (short)(i + 1);
        s_nunm = cnt;
    }
    __syncthreads();
    const int nunm = s_nunm;

    // ---- augmenting paths for unmatched rows (Dijkstra w/ deferred updates) ----
    for (int ii = 0; ii < nunm; ++ii) {
        const int i = sunm[ii];
        float shortestj = INF_F;   // absolute shortest-path cost to column j
        bool  used = false;
        int   myrow = 0;           // row matched to my column when it became used
        if (t == 0) sp[0] = (short)i;
        __syncthreads();

        int   j0 = 0;
        float minVal = 0.0f;
        int   step = 0;
        for (;;) {
            const int i0 = sp[j0];
            if (j == j0) { used = true; myrow = i0; }

            if (!used) {
                const float dx = spx[i0 - 1] - tx;
                const float dy = spy[i0 - 1] - ty;
                const float dz = spz[i0 - 1] - tz;
                const float cur = minVal - su[i0] - v +
                                  sqrtf(fmaf(dx, dx, fmaf(dy, dy, dz * dz)));
                if (cur < shortestj) { shortestj = cur; sway[j] = (short)j0; }
            }

            // ---- block argmin over free columns (1 barrier) ----
            const unsigned key  = fmap(used ? INF_F : shortestj);
            const unsigned wmin = __reduce_min_sync(0xffffffffu, key);
            const unsigned ball = __ballot_sync(0xffffffffu, key == wmin);
            const int lane = __ffs(ball) - 1;
            const int widx = __shfl_sync(0xffffffffu, j, lane);
            const int buf = step & 1;
            if ((t & 31) == 0)
                rbuf[buf][t >> 5] = ((unsigned long long)wmin << 32) | (unsigned)widx;
            __syncthreads();

            unsigned long long best = rbuf[buf][0];
            #pragma unroll
            for (int w = 1; w < 8; ++w) {
                const unsigned long long x = rbuf[buf][w];
                if (x < best) best = x;
            }
            minVal = funmap((unsigned)(best >> 32));
            const int j1 = (int)(best & 0xffffffffu);

            if (sp[j1] == 0) {
                // sink found: everyone has read sp[j1]; now safe to mutate
                __syncthreads();
                if (used) {
                    const float d = minVal - shortestj;
                    v -= d;
                    su[myrow] += d;    // distinct rows per used column: no conflict
                }
                if (t == 0) {
                    su[i] += minVal;
                    int jj = j1;
                    while (jj) {
                        const int jn = sway[jj];
                        sp[jj] = sp[jn];
                        jj = jn;
                    }
                }
                __syncthreads();
                break;
            }
            j0 = j1;
            ++step;
        }
    }

    // ---- matched distance for my column: row sp[j]-1 <-> target[j-1] ----
    const int r = sp[j] - 1;
    const float dx = spx[r] - tx;
    const float dy = spy[r] - ty;
    const float dz = spz[r] - tz;
    float md = sqrtf(fmaf(dx, dx, fmaf(dy, dy, dz * dz)));

    #pragma unroll
    for (int o = 16; o > 0; o >>= 1)
        md += __shfl_down_sync(0xffffffffu, md, o);
    if ((t & 31) == 0) fsum[t >> 5] = md;
    __syncthreads();
    if (t == 0) {
        float s = 0.0f;
        #pragma unroll
        for (int w = 0; w < 8; ++w) s += fsum[w];
        g_batch_sum[b] = s;
    }
}

__global__ void finalize_kernel(float* __restrict__ out)
{
    double s = 0.0;
    #pragma unroll
    for (int b = 0; b < BATCH; ++b) s += (double)g_batch_sum[b];
    out[0] = (float)(s / (double)BATCH);
}

extern "C" void kernel_launch(void* const* d_in, const int* in_sizes, int n_in,
                              void* d_out, int out_size)
{
    const float* pred   = (const float*)d_in[0];
    const float* target = (const float*)d_in[1];
    float* out = (float*)d_out;

    hungarian_kernel<<<BATCH, NT>>>(pred, target);
    finalize_kernel<<<1, 1>>>(out);
}